// round 6
// baseline (speedup 1.0000x reference)
#include <cuda_runtime.h>
#include <cstdint>

#define NC 32
#define NSTEPS 32
#define DDIM 30
#define TPB 128
#define PPT 8   // 8 consecutive points per thread, all via LDS

// Lane-replicated table with 33 cells (cell 32 duplicates cell 31 so that
// saturate(x)==1.0 maps correctly): tab[cell*32 + lane]. Lane l always reads
// banks (2l, 2l+1) -> conflict-free regardless of data-dependent cells.
__global__ __launch_bounds__(TPB) void cpab_kernel(
    const float4* __restrict__ points4,
    const float* __restrict__ theta,
    const float* __restrict__ basis,
    float4* __restrict__ out4,
    int n_points)
{
    __shared__ float2 tab[33 * 32];
    __shared__ float2 coef[NC];

    const int t   = blockIdx.y;
    const int tid = threadIdx.x;

    // ---- build per-theta coefficients (x-space: x' = e^a x + b*dT*phi) ----
    if (tid < NC) {
        const int c = tid;
        const float* __restrict__ th = theta + t * DDIM;
        const float* __restrict__ ba = basis + (2 * c) * DDIM;
        const float* __restrict__ bb = basis + (2 * c + 1) * DDIM;
        float a = 0.0f, b = 0.0f;
        #pragma unroll
        for (int j = 0; j < DDIM; j++) {
            a = fmaf(ba[j], th[j], a);
            b = fmaf(bb[j], th[j], b);
        }
        const float dT = 1.0f / (float)NSTEPS;
        float ad = dT * a;
        float bd = dT * b;
        float phi = (fabsf(ad) < 1e-6f) ? (1.0f + 0.5f * ad) : (expm1f(ad) / ad);
        coef[c] = make_float2(expf(ad), bd * phi);
    }
    __syncthreads();

    // replicate across 32 lane slots; cell 32 = cell 31 (saturate overflow)
    #pragma unroll
    for (int i = tid; i < 33 * 32; i += TPB) {
        int c = i >> 5;
        tab[i] = coef[c > 31 ? 31 : c];
    }
    __syncthreads();

    const int lane = tid & 31;
    const uint32_t sbase =
        (uint32_t)__cvta_generic_to_shared(tab) + (uint32_t)(lane * 8);

    // ---- load 8 consecutive points (2x float4) ----
    const int f4 = blockIdx.x * (TPB * 2) + tid * 2;
    float4 p0 = points4[f4];
    float4 p1 = points4[f4 + 1];

    float x[PPT];
    x[0] = p0.x;  x[1] = p0.y;  x[2] = p0.z;  x[3] = p0.w;
    x[4] = p1.x;  x[5] = p1.y;  x[6] = p1.z;  x[7] = p1.w;

    #pragma unroll 2
    for (int s = 0; s < NSTEPS; s++) {
        #pragma unroll
        for (int k = 0; k < PPT; k++) {
            // 5-instruction lookup:
            //   FADD.SAT : v = clamp(x, 0, 1)
            //   FFMA.RZ  : u = 32*v + 2^23  -> low bits = floor(32v) in [0,32]
            //   LEA      : addr = sbase + cell*256
            //   LDS.64   : (ea, bp)
            //   FFMA     : x = ea*x + bp
            float v = __saturatef(x[k]);
            float u;
            asm("fma.rz.f32 %0, %1, 0f42000000, 0f4B000000;" : "=f"(u) : "f"(v));
            uint32_t addr = sbase + (((uint32_t)__float_as_int(u)) << 8);
            float ea, bp;
            asm("ld.shared.v2.f32 {%0, %1}, [%2];"
                : "=f"(ea), "=f"(bp) : "r"(addr));
            x[k] = fmaf(ea, x[k], bp);
        }
    }

    float4 o0, o1;
    o0.x = x[0];  o0.y = x[1];  o0.z = x[2];  o0.w = x[3];
    o1.x = x[4];  o1.y = x[5];  o1.z = x[6];  o1.w = x[7];

    float4* __restrict__ op = out4 + ((size_t)t * n_points) / 4;
    op[f4]     = o0;
    op[f4 + 1] = o1;
}

extern "C" void kernel_launch(void* const* d_in, const int* in_sizes, int n_in,
                              void* d_out, int out_size) {
    const float* points = (const float*)d_in[0];   // [1, n_points]
    const float* theta  = (const float*)d_in[1];   // [n_theta, 30]
    const float* basis  = (const float*)d_in[2];   // [64, 30]
    float* out = (float*)d_out;                    // [n_theta, 1, n_points]

    const int n_points = in_sizes[0];
    const int n_theta  = in_sizes[1] / DDIM;

    dim3 grid(n_points / (TPB * PPT), n_theta);
    cpab_kernel<<<grid, TPB>>>((const float4*)points, theta, basis,
                               (float4*)out, n_points);
}

// round 7
// speedup vs baseline: 1.0156x; 1.0156x over previous
#include <cuda_runtime.h>
#include <cstdint>

#define NC 32
#define NSTEPS 32
#define DDIM 30
#define TPB 128
#define PPT 8   // 4 chains via LDS + 4 chains via SHFL

// LDS table: 33 cells (cell 32 duplicates 31 for saturate(x)==1.0),
// lane-replicated: tab[cell*32 + lane] -> conflict-free by construction.
__global__ __launch_bounds__(TPB) void cpab_kernel(
    const float4* __restrict__ points4,
    const float* __restrict__ theta,
    const float* __restrict__ basis,
    float4* __restrict__ out4,
    int n_points)
{
    __shared__ float2 tab[33 * 32];
    __shared__ float2 coef[NC];

    const int t   = blockIdx.y;
    const int tid = threadIdx.x;

    // ---- per-theta coefficients (x-space: x' = e^{a dT} x + b dT phi) ----
    if (tid < NC) {
        const int c = tid;
        const float* __restrict__ th = theta + t * DDIM;
        const float* __restrict__ ba = basis + (2 * c) * DDIM;
        const float* __restrict__ bb = basis + (2 * c + 1) * DDIM;
        float a = 0.0f, b = 0.0f;
        #pragma unroll
        for (int j = 0; j < DDIM; j++) {
            a = fmaf(ba[j], th[j], a);
            b = fmaf(bb[j], th[j], b);
        }
        const float dT = 1.0f / (float)NSTEPS;
        float ad = dT * a;
        float bd = dT * b;
        float phi = (fabsf(ad) < 1e-6f) ? (1.0f + 0.5f * ad) : (expm1f(ad) / ad);
        coef[c] = make_float2(expf(ad), bd * phi);
    }
    __syncthreads();

    #pragma unroll
    for (int i = tid; i < 33 * 32; i += TPB) {
        int c = i >> 5;
        tab[i] = coef[c > 31 ? 31 : c];
    }
    __syncthreads();

    const int lane = tid & 31;
    // register table for the SHFL path: lane l owns cell l
    const float ea_r = coef[lane].x;
    const float bp_r = coef[lane].y;

    const uint32_t sbase =
        (uint32_t)__cvta_generic_to_shared(tab) + (uint32_t)(lane * 8);

    // ---- 8 consecutive points (2x float4) ----
    const int f4 = blockIdx.x * (TPB * 2) + tid * 2;
    float4 p0 = points4[f4];
    float4 p1 = points4[f4 + 1];

    float x[PPT];
    x[0] = p0.x;  x[1] = p0.y;  x[2] = p0.z;  x[3] = p0.w;
    x[4] = p1.x;  x[5] = p1.y;  x[6] = p1.z;  x[7] = p1.w;

    #pragma unroll 2
    for (int s = 0; s < NSTEPS; s++) {
        // chains 0..3: LDS path, 5 instructions per lookup
        #pragma unroll
        for (int k = 0; k < 4; k++) {
            float v = __saturatef(x[k]);
            float u;
            asm("fma.rz.f32 %0, %1, 0f42000000, 0f4B000000;" : "=f"(u) : "f"(v));
            uint32_t addr = sbase + (((uint32_t)__float_as_int(u)) << 8);
            float ea, bp;
            asm("ld.shared.v2.f32 {%0, %1}, [%2];"
                : "=f"(ea), "=f"(bp) : "r"(addr));
            x[k] = fmaf(ea, x[k], bp);
        }
        // chains 4..7: SHFL path, 6 instructions per lookup
        #pragma unroll
        for (int k = 4; k < PPT; k++) {
            float v = __saturatef(x[k]);
            float u;
            asm("fma.rz.f32 %0, %1, 0f42000000, 0f4B000000;" : "=f"(u) : "f"(v));
            // cap cell at 31 (bits = 0x4B000000 + cell; shfl masks low 5 bits)
            int idx = min(__float_as_int(u), 0x4B00001F);
            float ea = __shfl_sync(0xffffffffu, ea_r, idx);
            float bp = __shfl_sync(0xffffffffu, bp_r, idx);
            x[k] = fmaf(ea, x[k], bp);
        }
    }

    float4 o0, o1;
    o0.x = x[0];  o0.y = x[1];  o0.z = x[2];  o0.w = x[3];
    o1.x = x[4];  o1.y = x[5];  o1.z = x[6];  o1.w = x[7];

    float4* __restrict__ op = out4 + ((size_t)t * n_points) / 4;
    op[f4]     = o0;
    op[f4 + 1] = o1;
}

extern "C" void kernel_launch(void* const* d_in, const int* in_sizes, int n_in,
                              void* d_out, int out_size) {
    const float* points = (const float*)d_in[0];   // [1, n_points]
    const float* theta  = (const float*)d_in[1];   // [n_theta, 30]
    const float* basis  = (const float*)d_in[2];   // [64, 30]
    float* out = (float*)d_out;                    // [n_theta, 1, n_points]

    const int n_points = in_sizes[0];
    const int n_theta  = in_sizes[1] / DDIM;

    dim3 grid(n_points / (TPB * PPT), n_theta);
    cpab_kernel<<<grid, TPB>>>((const float4*)points, theta, basis,
                               (float4*)out, n_points);
}